// round 16
// baseline (speedup 1.0000x reference)
#include <cuda_runtime.h>
#include <cstdint>

// ---------------------------------------------------------------------------
// DynamicConvBlock: fused 65-tap combined depthwise conv + ReLU + 1x1 conv.
//   x:(8,192,96,96) f32 -> out:(8,64,96,96) f32
// Stage 1: conv kernel (PROW=24 row blocking) -> g_midh fp16x2 ch-pair mid.
// Stage 0: prep_w_frag: W -> fp16 A-fragments (m16n8k16 lane order).
// Stage 2: pointwise_tc2: mma.sync.m16n8k16 f16 single pass, direct-B.
// Launch order conv, prep, pw (prep only feeds pw) so ncu captures conv.
// ---------------------------------------------------------------------------

#define NB   8
#define NC   192
#define NCP  96
#define NH   96
#define NW   96
#define HW   (NH*NW)     // 9216
#define NOC  64
#define TAPS 65
#define PROW 24
#define KS16 12          // 192 / 16

// scratch
__device__ uint32_t g_midh[(size_t)NB * NCP * HW]; // 28.3 MB fp16x2 (ch pair)
__device__ uint4 g_wah[4 * KS16 * 32];             // A-fragments f16 (24 KB)

// ---- tap tables ------------------------------------------------------------
__device__ constexpr int SEC_DX[11]   = {-7,-5,-3,-2,-1, 0, 1, 2, 3, 5, 7};
__device__ constexpr int SEC_BASE[11] = {-7,-5,-3,-3,-3,-7,-3,-3,-3,-5,-7};
__device__ constexpr int SEC_W[11]    = {38,34,30,30,30,38,30,30,30,34,38};  // PROW + span
__device__ constexpr int SEC_N[11]    = { 3, 3, 7, 7, 7,11, 7, 7, 7, 3, 3};
__device__ constexpr int SEC_OFF[11]  = { 0, 3, 6,13,20,27,38,45,52,59,62};

__device__ constexpr int DY_FLAT[TAPS] = {
    -7,0,7, -5,0,5,
    -3,-2,-1,0,1,2,3, -3,-2,-1,0,1,2,3, -3,-2,-1,0,1,2,3,
    -7,-5,-3,-2,-1,0,1,2,3,5,7,
    -3,-2,-1,0,1,2,3, -3,-2,-1,0,1,2,3, -3,-2,-1,0,1,2,3,
    -5,0,5, -7,0,7
};
__device__ constexpr int DX_FLAT[TAPS] = {
    -7,-7,-7, -5,-5,-5,
    -3,-3,-3,-3,-3,-3,-3, -2,-2,-2,-2,-2,-2,-2, -1,-1,-1,-1,-1,-1,-1,
     0,0,0,0,0,0,0,0,0,0,0,
     1,1,1,1,1,1,1, 2,2,2,2,2,2,2, 3,3,3,3,3,3,3,
     5,5,5, 7,7,7
};

// ---- helpers ---------------------------------------------------------------
__device__ __forceinline__ unsigned long long fma2_(unsigned long long a,
                                                    unsigned long long b,
                                                    unsigned long long c) {
    unsigned long long d;
    asm("fma.rn.f32x2 %0, %1, %2, %3;" : "=l"(d) : "l"(a), "l"(b), "l"(c));
    return d;
}
__device__ __forceinline__ float2 unpk2_(unsigned long long v) {
    float2 f;
    asm("mov.b64 {%0, %1}, %2;" : "=f"(f.x), "=f"(f.y) : "l"(v));
    return f;
}
// pack two f32 -> f16x2 (first arg -> low half)
__device__ __forceinline__ uint32_t packh(float lo, float hi) {
    uint32_t r;
    asm("cvt.rn.f16x2.f32 %0, %1, %2;" : "=r"(r) : "f"(hi), "f"(lo));
    return r;
}
__device__ __forceinline__ void mma_f16(float* d, uint4 a,
                                        uint32_t b0, uint32_t b1) {
    asm("mma.sync.aligned.m16n8k16.row.col.f32.f16.f16.f32 "
        "{%0,%1,%2,%3}, {%4,%5,%6,%7}, {%8,%9}, {%0,%1,%2,%3};"
        : "+f"(d[0]), "+f"(d[1]), "+f"(d[2]), "+f"(d[3])
        : "r"(a.x), "r"(a.y), "r"(a.z), "r"(a.w), "r"(b0), "r"(b1));
}

// ---- fold the 7 weight tensors + a[] into one 65-tap weight ----------------
__device__ __forceinline__ float fold_weight(int c, int t,
                                             const float* __restrict__ a,
                                             const float* __restrict__ k1,
                                             const float* __restrict__ k3,
                                             const float* __restrict__ k5,
                                             const float* __restrict__ k7,
                                             const float* __restrict__ k3d5,
                                             const float* __restrict__ k3d7) {
    int dy = DY_FLAT[t], dx = DX_FLAT[t];
    float w = 0.0f;
    if (abs(dy) <= 3 && abs(dx) <= 3) w += a[4] * k7[c * 49 + (dy + 3) * 7 + (dx + 3)];
    if (abs(dy) <= 2 && abs(dx) <= 2) w += a[3] * k5[c * 25 + (dy + 2) * 5 + (dx + 2)];
    if (abs(dy) <= 1 && abs(dx) <= 1) w += (a[2] + a[5]) * k3[c * 9 + (dy + 1) * 3 + (dx + 1)];
    if (dy == 0 && dx == 0)           w += a[0] + a[1] * k1[c];
    if ((dy == -5 || dy == 0 || dy == 5) && (dx == -5 || dx == 0 || dx == 5))
        w += a[6] * k3d5[c * 9 + (dy / 5 + 1) * 3 + (dx / 5 + 1)];
    if ((dy == -7 || dy == 0 || dy == 7) && (dx == -7 || dx == 0 || dx == 7))
        w += a[7] * k3d7[c * 9 + (dy / 7 + 1) * 3 + (dx / 7 + 1)];
    return w;
}

// ---------------------------------------------------------------------------
// Stage 0: fp16 A-fragments for mma.m16n8k16.row (A = W[64,192]).
// ---------------------------------------------------------------------------
__global__ void prep_w_frag(const float* __restrict__ wp) {
    int i = blockIdx.x * 256 + threadIdx.x;
    if (i >= 4 * KS16 * 32) return;
    int lane = i & 31;
    int f    = i >> 5;
    int mt   = f / KS16;
    int ks   = f - mt * KS16;
    int r = mt * 16 + (lane >> 2);
    int c = ks * 16 + (lane & 3) * 2;

    g_wah[i] = make_uint4(
        packh(wp[r * NC + c],           wp[r * NC + c + 1]),
        packh(wp[(r + 8) * NC + c],     wp[(r + 8) * NC + c + 1]),
        packh(wp[r * NC + c + 8],       wp[r * NC + c + 9]),
        packh(wp[(r + 8) * NC + c + 8], wp[(r + 8) * NC + c + 9]));
}

// ---------------------------------------------------------------------------
// Stage 1: depthwise conv + ReLU -> fp16x2 channel-pair mid. PROW = 24.
// ---------------------------------------------------------------------------
#define SM_ROWS 38
#define SM_PITCH 112

__global__ void __launch_bounds__(96)
conv_kernel(const float* __restrict__ x,
            const float* __restrict__ a,
            const float* __restrict__ k1,
            const float* __restrict__ k3,
            const float* __restrict__ k5,
            const float* __restrict__ k7,
            const float* __restrict__ k3d5,
            const float* __restrict__ k3d7) {
    __shared__ float2 sm[SM_ROWS][SM_PITCH];
    __shared__ float2 sw[TAPS];

    const int tid = threadIdx.x;
    const int bc  = blockIdx.y;                     // b*96 + cp
    const int b   = bc / NCP;
    const int cp  = bc - b * NCP;
    const int c0  = cp * 2;
    const int h0  = blockIdx.x * PROW;              // 0,24,48,72

    {
        float4* smf = reinterpret_cast<float4*>(&sm[0][0]);
        for (int i = tid; i < SM_ROWS * SM_PITCH / 2; i += 96)
            smf[i] = make_float4(0.f, 0.f, 0.f, 0.f);
    }

    for (int i = tid; i < 2 * TAPS; i += 96) {
        int t = i >> 1, half = i & 1;
        float w = fold_weight(c0 + half, t, a, k1, k3, k5, k7, k3d5, k3d7);
        reinterpret_cast<float*>(&sw[t])[half] = w;
    }
    __syncthreads();

    const size_t xbase = ((size_t)b * NC + c0) * HW;
    {
        const int r0 = (h0 >= 7) ? 0 : 7 - h0;
        const int r1 = (h0 + PROW + 7 <= NH) ? SM_ROWS : (NH + 7 - h0);
        const float* px0 = x + xbase + (size_t)(h0 - 7) * NW + tid;
        for (int r = r0; r < r1; r++) {
            float2 v;
            v.x = px0[(size_t)r * NW];
            v.y = px0[(size_t)r * NW + HW];
            sm[r][tid + 7] = v;
        }
    }
    __syncthreads();

    const int col = tid + 7;
    const unsigned long long* swq = reinterpret_cast<const unsigned long long*>(sw);

    unsigned long long acc[PROW];
#pragma unroll
    for (int p = 0; p < PROW; p++) acc[p] = 0ull;

#pragma unroll
    for (int s = 0; s < 11; s++) {
        const int bse = SEC_BASE[s];
        const int wl  = SEC_W[s];
        const int nd  = SEC_N[s];
        const int off = SEC_OFF[s];
        const int cx  = col + SEC_DX[s];

        unsigned long long wv[11];
#pragma unroll
        for (int j = 0; j < nd; j++) wv[j] = swq[off + j];

#pragma unroll
        for (int i = 0; i < wl; i++) {
            unsigned long long v =
                *reinterpret_cast<const unsigned long long*>(&sm[bse + 7 + i][cx]);
#pragma unroll
            for (int j = 0; j < nd; j++) {
                const int p = i - (DY_FLAT[off + j] - bse);
                if (p >= 0 && p < PROW)
                    acc[p] = fma2_(v, wv[j], acc[p]);
            }
        }
    }

    // ---- ReLU + pack channel pair to fp16x2, single coalesced store ----
    uint32_t* m0 = g_midh + (size_t)bc * HW + (size_t)h0 * NW + tid;
#pragma unroll
    for (int p = 0; p < PROW; p++) {
        float2 v = unpk2_(acc[p]);
        v.x = fmaxf(v.x, 0.0f);
        v.y = fmaxf(v.y, 0.0f);
        m0[(size_t)p * NW] = packh(v.x, v.y);       // low = even ch, high = odd
    }
}

// ---------------------------------------------------------------------------
// Stage 2: pointwise 1x1 conv 192->64, mma.sync.m16n8k16 f16, single pass.
// (unchanged from R15: 81.8us version)
// ---------------------------------------------------------------------------
__global__ void __launch_bounds__(128)
pointwise_tc2(float* __restrict__ out) {
    const int tid  = threadIdx.x;
    const int lane = tid & 31;
    const int wt   = tid >> 5;                      // warp's px quarter

    const int pixglob = blockIdx.x * 128 + wt * 32; // 128 | 9216
    const int b   = pixglob / HW;
    const int pix = pixglob - b * HW;

    const int kr = lane & 3;                        // k-pair row
    const int np = lane >> 2;                       // px within subtile

    const uint32_t* midb = g_midh + (size_t)b * NCP * HW + pix + np;
    const uint4* wah = g_wah + lane;

    float acc[4][4][4];                             // [mt][subtile][4]
#pragma unroll
    for (int m = 0; m < 4; m++)
#pragma unroll
        for (int s = 0; s < 4; s++)
#pragma unroll
            for (int q = 0; q < 4; q++) acc[m][s][q] = 0.0f;

#pragma unroll 1
    for (int ks = 0; ks < KS16; ks++) {
        uint4 Ah[4];
#pragma unroll
        for (int m = 0; m < 4; m++)
            Ah[m] = wah[(m * KS16 + ks) * 32];

        const uint32_t* mk = midb + (size_t)(ks * 8 + kr) * HW;
        uint32_t b0[4], b1[4];
#pragma unroll
        for (int s = 0; s < 4; s++) {
            b0[s] = mk[s * 8];
            b1[s] = mk[(size_t)4 * HW + s * 8];
        }

#pragma unroll
        for (int s = 0; s < 4; s++) {
#pragma unroll
            for (int m = 0; m < 4; m++)
                mma_f16(acc[m][s], Ah[m], b0[s], b1[s]);
        }
    }

    const int g  = lane >> 2;
    const int t4 = lane & 3;
#pragma unroll
    for (int m = 0; m < 4; m++) {
        float* o0 = out + ((size_t)(b * NOC + m * 16 + g)) * HW + pix + 2 * t4;
        float* o1 = o0 + (size_t)8 * HW;
#pragma unroll
        for (int s = 0; s < 4; s++) {
            *reinterpret_cast<float2*>(o0 + s * 8) =
                make_float2(acc[m][s][0], acc[m][s][1]);
            *reinterpret_cast<float2*>(o1 + s * 8) =
                make_float2(acc[m][s][2], acc[m][s][3]);
        }
    }
}

// ---------------------------------------------------------------------------
extern "C" void kernel_launch(void* const* d_in, const int* in_sizes, int n_in,
                              void* d_out, int out_size) {
    const float* x    = (const float*)d_in[0];
    const float* a    = (const float*)d_in[1];
    const float* k1   = (const float*)d_in[2];
    const float* k3   = (const float*)d_in[3];
    const float* k5   = (const float*)d_in[4];
    const float* k7   = (const float*)d_in[5];
    const float* k3d5 = (const float*)d_in[6];
    const float* k3d7 = (const float*)d_in[7];
    const float* wp   = (const float*)d_in[8];
    float* out = (float*)d_out;

    // conv first (prep only feeds pointwise) -> ncu lands on conv
    conv_kernel<<<dim3(NH / PROW, NB * NCP), 96>>>(x, a, k1, k3, k5, k7, k3d5, k3d7);
    prep_w_frag<<<(4 * KS16 * 32 + 255) / 256, 256>>>(wp);
    pointwise_tc2<<<NB * HW / 128, 128>>>(out);
}